// round 17
// baseline (speedup 1.0000x reference)
#include <cuda_runtime.h>
#include <cuda_fp16.h>
#include <math.h>

#define NN 100000
#define NE 3200000
#define FULLMASK 0xffffffffu
#define GB1      ((NN + 255) / 256)   // 391 gemm blocks (layer1)
#define SB       2048                 // scatter blocks in fused kernel
#define CAP      96                   // slab capacity per dst (P(deg>96) ~ 1e-20)

// ---------------- scratch (device globals; no runtime allocation) ----------------
// meta record: (src, u as broadcast half2)
__device__ int2     g_se[(size_t)NN * CAP];  // slab-sorted (src, uh2-bits)
__device__ int      g_cur[NN];               // cursors; zero at load AND re-zeroed by agg2

// pair-interleaved tables: record p (8B) = { half2(y0[2p],y0[2p+1]), half2(y1[2p],y1[2p+1]) }
__device__ uint2   g_y01p[NN * 16];   // layer1: 16 pairs/node (32 feats)
__device__ float   g_r1 [NN * 32];
__device__ float   g_h  [NN * 32];

__device__ uint2   g_z01p[NN * 8];    // layer2: 8 pairs/node (16 feats)
__device__ float   g_r2 [NN * 16];

// ---------------- GEMM body: one node per thread, pair-interleaved pack out ----
template<int FO, int TPB>
__device__ __forceinline__ void gemm_body(
    const float* __restrict__ xin,
    const float* __restrict__ W,      // [2,32,FO]
    const float* __restrict__ root,   // [32,FO]
    uint2*  __restrict__ packp,       // [NN * FO/2]
    float*  __restrict__ rout,        // [NN * FO]
    int base)
{
    __shared__ __align__(16) float sW0[32 * FO];
    __shared__ __align__(16) float sW1[32 * FO];
    __shared__ __align__(16) float sR [32 * FO];
    int tid = threadIdx.x;

    for (int i = tid; i < 32 * FO; i += TPB) {
        sW0[i] = W[i];
        sW1[i] = W[32 * FO + i];
        sR [i] = root[i];
    }

    int n = base + tid;
    float xr[32];
#pragma unroll
    for (int q = 0; q < 8; q++) {
        float4 v = make_float4(0.f, 0.f, 0.f, 0.f);
        if (n < NN) v = *reinterpret_cast<const float4*>(&xin[(size_t)n * 32 + q * 4]);
        xr[q*4+0] = v.x; xr[q*4+1] = v.y; xr[q*4+2] = v.z; xr[q*4+3] = v.w;
    }
    __syncthreads();

#pragma unroll
    for (int jg = 0; jg < FO / 4; jg++) {
        float4 ay0 = make_float4(0.f,0.f,0.f,0.f);
        float4 ay1 = ay0, ar = ay0;
#pragma unroll
        for (int k = 0; k < 32; k++) {
            float4 w0 = *reinterpret_cast<const float4*>(&sW0[k * FO + jg * 4]);
            float4 w1 = *reinterpret_cast<const float4*>(&sW1[k * FO + jg * 4]);
            float4 wr = *reinterpret_cast<const float4*>(&sR [k * FO + jg * 4]);
            float xk = xr[k];
            ay0.x += xk*w0.x; ay0.y += xk*w0.y; ay0.z += xk*w0.z; ay0.w += xk*w0.w;
            ay1.x += xk*w1.x; ay1.y += xk*w1.y; ay1.z += xk*w1.z; ay1.w += xk*w1.w;
            ar.x  += xk*wr.x; ar.y  += xk*wr.y; ar.z  += xk*wr.z; ar.w  += xk*wr.w;
        }
        if (n < NN) {
            // pair 2jg = feats (4jg,4jg+1); pair 2jg+1 = feats (4jg+2,4jg+3)
            __half2 h[4];
            h[0] = __floats2half2_rn(ay0.x, ay0.y);   // y0 pair 2jg
            h[1] = __floats2half2_rn(ay1.x, ay1.y);   // y1 pair 2jg
            h[2] = __floats2half2_rn(ay0.z, ay0.w);   // y0 pair 2jg+1
            h[3] = __floats2half2_rn(ay1.z, ay1.w);   // y1 pair 2jg+1
            *reinterpret_cast<float4*>(&packp[n * (FO / 2) + jg * 2]) =
                *reinterpret_cast<float4*>(h);
            *reinterpret_cast<float4*>(&rout[(size_t)n * FO + jg * 4]) =
                make_float4(ar.x, ar.y, ar.z, ar.w);
        }
    }
}

// ---------------- fused: layer1 GEMM (blocks < GB1) + slab scatter ----------
__global__ __launch_bounds__(256) void gemm1_scatter(
    const float* __restrict__ x,
    const float* __restrict__ W,
    const float* __restrict__ root,
    const int*   __restrict__ ei32,
    const float* __restrict__ ea)
{
    if (blockIdx.x < GB1) {
        gemm_body<32, 256>(x, W, root, g_y01p, g_r1, blockIdx.x * 256);
        return;
    }

    // per-block int64-vs-int32 layout detection (64-thread vote)
    __shared__ int s_nz;
    if (threadIdx.x == 0) s_nz = 0;
    __syncthreads();
    if (threadIdx.x < 64 && ei32[2 * threadIdx.x + 1] != 0)
        atomicAdd(&s_nz, 1);
    __syncthreads();
    int is64 = (s_nz == 0);

    int b = blockIdx.x - GB1;
    for (int e = b * 256 + threadIdx.x; e < NE; e += SB * 256) {
        int s, d;
        if (is64) {
            s = ei32[2 * e];
            d = ei32[2 * (NE + e)];
        } else {
            s = ei32[e];
            d = ei32[NE + e];
        }
        s = min(max(s, 0), NN - 1);
        d = min(max(d, 0), NN - 1);
        float u = fminf(fmaxf(ea[e], 0.0f), 1.0f);
        __half2 uh2 = __float2half2_rn(u);          // broadcast u once at scatter time
        int pos = atomicAdd(&g_cur[d], 1);
        if (pos < CAP)
            g_se[(size_t)d * CAP + pos] =
                make_int2(s, (int)*reinterpret_cast<unsigned*>(&uh2));
    }
}

// ---------------- layer2 GEMM: 128-thr blocks (2x grid, better latency hiding) -
__global__ __launch_bounds__(128) void gemm2_kernel(
    const float* __restrict__ W,
    const float* __restrict__ root)
{
    gemm_body<16, 128>(g_h, W, root, g_z01p, g_r2, blockIdx.x * 128);
}

// fp16 lerp (HSUB2+HFMA2), fp32 accumulate — used in agg1 (measured win there)
__device__ __forceinline__ void lerp2_acc_h(float2& acc, uint2 g, int uh2bits) {
    __half2 h0 = *reinterpret_cast<__half2*>(&g.x);
    __half2 h1 = *reinterpret_cast<__half2*>(&g.y);
    __half2 u2 = *reinterpret_cast<__half2*>(&uh2bits);
    __half2 m  = __hfma2(u2, __hsub2(h1, h0), h0);
    float2 mf = __half22float2(m);
    acc.x += mf.x;
    acc.y += mf.y;
}

// fp32 lerp — used in agg2 (measured faster there; lower reg pressure)
__device__ __forceinline__ void lerp2_acc_f(float2& acc, uint2 g, int uh2bits) {
    float2 f0 = __half22float2(*reinterpret_cast<__half2*>(&g.x));
    float2 f1 = __half22float2(*reinterpret_cast<__half2*>(&g.y));
    float u = __low2float(*reinterpret_cast<__half2*>(&uh2bits));
    acc.x += fmaf(u, f1.x - f0.x, f0.x);
    acc.y += fmaf(u, f1.y - f0.y, f0.y);
}

// ---------------- layer1 aggregation: warp/node, 16 lanes x 2 feats, 2 edges ---
__global__ __launch_bounds__(256) void edge_agg1(const float* __restrict__ b1) {
    int tid = blockIdx.x * blockDim.x + threadIdx.x;
    int w = tid >> 5;
    int lane = threadIdx.x & 31;
    if (w >= NN) return;
    int cnt = min(g_cur[w], CAP);
    const int2* slab = g_se + (size_t)w * CAP;
    int half = lane >> 4;        // edge parity
    int p    = lane & 15;        // feature pair

    float2 acc = make_float2(0.f, 0.f);
    int e = half;
    // 16-edge window: 8 gathers in flight per lane
    for (; e + 14 < cnt; e += 16) {
        int2 m0 = slab[e],    m1 = slab[e+2],  m2 = slab[e+4],  m3 = slab[e+6];
        int2 m4 = slab[e+8],  m5 = slab[e+10], m6 = slab[e+12], m7 = slab[e+14];
        uint2 g0 = g_y01p[m0.x * 16 + p];
        uint2 g1 = g_y01p[m1.x * 16 + p];
        uint2 g2 = g_y01p[m2.x * 16 + p];
        uint2 g3 = g_y01p[m3.x * 16 + p];
        uint2 g4 = g_y01p[m4.x * 16 + p];
        uint2 g5 = g_y01p[m5.x * 16 + p];
        uint2 g6 = g_y01p[m6.x * 16 + p];
        uint2 g7 = g_y01p[m7.x * 16 + p];
        lerp2_acc_h(acc, g0, m0.y); lerp2_acc_h(acc, g1, m1.y);
        lerp2_acc_h(acc, g2, m2.y); lerp2_acc_h(acc, g3, m3.y);
        lerp2_acc_h(acc, g4, m4.y); lerp2_acc_h(acc, g5, m5.y);
        lerp2_acc_h(acc, g6, m6.y); lerp2_acc_h(acc, g7, m7.y);
    }
    // 8-edge window
    for (; e + 6 < cnt; e += 8) {
        int2 m0 = slab[e], m1 = slab[e+2], m2 = slab[e+4], m3 = slab[e+6];
        uint2 g0 = g_y01p[m0.x * 16 + p];
        uint2 g1 = g_y01p[m1.x * 16 + p];
        uint2 g2 = g_y01p[m2.x * 16 + p];
        uint2 g3 = g_y01p[m3.x * 16 + p];
        lerp2_acc_h(acc, g0, m0.y); lerp2_acc_h(acc, g1, m1.y);
        lerp2_acc_h(acc, g2, m2.y); lerp2_acc_h(acc, g3, m3.y);
    }
    for (; e < cnt; e += 2) {
        int2 m = slab[e];
        lerp2_acc_h(acc, g_y01p[m.x * 16 + p], m.y);
    }
    acc.x += __shfl_xor_sync(FULLMASK, acc.x, 16);
    acc.y += __shfl_xor_sync(FULLMASK, acc.y, 16);

    float inv = 1.0f / fmaxf((float)cnt, 1.0f);
    float2 r = *reinterpret_cast<const float2*>(&g_r1[(size_t)w * 32 + 2 * p]);
    float2 b = *reinterpret_cast<const float2*>(&b1[2 * p]);
    float2 h;
    h.x = fmaxf(acc.x * inv + r.x + b.x, 0.0f);
    h.y = fmaxf(acc.y * inv + r.y + b.y, 0.0f);
    if (lane < 16)
        *reinterpret_cast<float2*>(&g_h[(size_t)w * 32 + 2 * p]) = h;
}

// ---------------- layer2 aggregation: warp/node, 8 lanes x 2 feats, 4 edges ----
// fp32 lerp; 32-edge deep window for MLP; fused log_softmax; resets cursor
__global__ __launch_bounds__(256) void edge_agg2(const float* __restrict__ b2,
                                                 float* __restrict__ out) {
    int tid = blockIdx.x * blockDim.x + threadIdx.x;
    int w = tid >> 5;
    int lane = threadIdx.x & 31;
    if (w >= NN) return;
    int cnt = min(g_cur[w], CAP);
    const int2* slab = g_se + (size_t)w * CAP;
    int grp = lane >> 3;         // edge slot mod 4
    int p   = lane & 7;          // feature pair

    float2 acc = make_float2(0.f, 0.f);
    int e = grp;
    // 32-edge window: 8 meta + 8 gathers in flight per lane-group
    for (; e + 28 < cnt; e += 32) {
        int2 m0 = slab[e],    m1 = slab[e+4],  m2 = slab[e+8],  m3 = slab[e+12];
        int2 m4 = slab[e+16], m5 = slab[e+20], m6 = slab[e+24], m7 = slab[e+28];
        uint2 g0 = g_z01p[m0.x * 8 + p];
        uint2 g1 = g_z01p[m1.x * 8 + p];
        uint2 g2 = g_z01p[m2.x * 8 + p];
        uint2 g3 = g_z01p[m3.x * 8 + p];
        uint2 g4 = g_z01p[m4.x * 8 + p];
        uint2 g5 = g_z01p[m5.x * 8 + p];
        uint2 g6 = g_z01p[m6.x * 8 + p];
        uint2 g7 = g_z01p[m7.x * 8 + p];
        lerp2_acc_f(acc, g0, m0.y); lerp2_acc_f(acc, g1, m1.y);
        lerp2_acc_f(acc, g2, m2.y); lerp2_acc_f(acc, g3, m3.y);
        lerp2_acc_f(acc, g4, m4.y); lerp2_acc_f(acc, g5, m5.y);
        lerp2_acc_f(acc, g6, m6.y); lerp2_acc_f(acc, g7, m7.y);
    }
    // 16-edge window
    for (; e + 12 < cnt; e += 16) {
        int2 m0 = slab[e], m1 = slab[e+4], m2 = slab[e+8], m3 = slab[e+12];
        uint2 g0 = g_z01p[m0.x * 8 + p];
        uint2 g1 = g_z01p[m1.x * 8 + p];
        uint2 g2 = g_z01p[m2.x * 8 + p];
        uint2 g3 = g_z01p[m3.x * 8 + p];
        lerp2_acc_f(acc, g0, m0.y); lerp2_acc_f(acc, g1, m1.y);
        lerp2_acc_f(acc, g2, m2.y); lerp2_acc_f(acc, g3, m3.y);
    }
    for (; e < cnt; e += 4) {
        int2 m = slab[e];
        lerp2_acc_f(acc, g_z01p[m.x * 8 + p], m.y);
    }
    // combine 4 edge groups
    acc.x += __shfl_xor_sync(FULLMASK, acc.x, 8);
    acc.y += __shfl_xor_sync(FULLMASK, acc.y, 8);
    acc.x += __shfl_xor_sync(FULLMASK, acc.x, 16);
    acc.y += __shfl_xor_sync(FULLMASK, acc.y, 16);

    float inv = 1.0f / fmaxf((float)cnt, 1.0f);
    float2 r = *reinterpret_cast<const float2*>(&g_r2[(size_t)w * 16 + 2 * p]);
    float2 b = *reinterpret_cast<const float2*>(&b2[2 * p]);
    float2 v;
    v.x = acc.x * inv + r.x + b.x;
    v.y = acc.y * inv + r.y + b.y;

    // log_softmax over 16 features (replicated across the 4 groups)
    float m = fmaxf(v.x, v.y);
#pragma unroll
    for (int off = 4; off >= 1; off >>= 1)
        m = fmaxf(m, __shfl_xor_sync(FULLMASK, m, off));
    float s = expf(v.x - m) + expf(v.y - m);
#pragma unroll
    for (int off = 4; off >= 1; off >>= 1)
        s += __shfl_xor_sync(FULLMASK, s, off);
    float lo = logf(s);
    if (lane < 8) {
        float2 o = make_float2(v.x - m - lo, v.y - m - lo);
        *reinterpret_cast<float2*>(&out[(size_t)w * 16 + 2 * p]) = o;
    }
    // reset cursor for the next graph replay (keeps kernel_launch deterministic)
    if (lane == 0) g_cur[w] = 0;
}

// ---------------- launch ----------------
extern "C" void kernel_launch(void* const* d_in, const int* in_sizes, int n_in,
                              void* d_out, int out_size) {
    const float* x   = (const float*)d_in[0];
    const int*   ei  = (const int*)d_in[1];
    const float* ea  = (const float*)d_in[2];
    const float* W1  = (const float*)d_in[3];
    const float* r1w = (const float*)d_in[4];
    const float* b1  = (const float*)d_in[5];
    const float* W2  = (const float*)d_in[6];
    const float* r2w = (const float*)d_in[7];
    const float* b2  = (const float*)d_in[8];
    float* out = (float*)d_out;

    gemm1_scatter<<<GB1 + SB, 256>>>(x, W1, r1w, ei, ea);
    edge_agg1<<<(NN * 32 + 255) / 256, 256>>>(b1);
    gemm2_kernel<<<(NN + 127) / 128, 128>>>(W2, r2w);
    edge_agg2<<<(NN * 32 + 255) / 256, 256>>>(b2, out);
}